// round 4
// baseline (speedup 1.0000x reference)
#include <cuda_runtime.h>
#include <cstdint>

// Problem constants (fixed shapes per reference)
#define N_NODES  100000
#define D_FEAT   64
#define OUT_COLS 65
#define MAXDEG   48            // Poisson(12): P(deg>48) ~ 0 over 100K nodes; overflow path keeps correctness anyway
#define OVF_CAP  1300000       // >= E, overflow list can never drop edges

// Static scratch (allocation-guard-safe). Zero-initialized at module load;
// kernels re-zero what they consume so every kernel_launch call starts clean.
__device__ int  g_count[N_NODES];                       // per-node degree counters
__device__ int  g_ovf_count;                            // overflow edge count
__device__ int  g_ovf_edges[OVF_CAP];                   // overflow edge indices
__device__ int2 g_slots[(size_t)N_NODES * MAXDEG];      // {src_idx, bitcast(e_feat)}

// ---------------------------------------------------------------------------
// Kernel 1: bin edges by destination node into padded slots.
// One thread per edge. Int atomics only (spread addresses -> cheap).
// ---------------------------------------------------------------------------
__global__ void bin_kernel(const float* __restrict__ e_feat,
                           const int*   __restrict__ src_idx,
                           const int*   __restrict__ dst_idx,
                           int E) {
    int e = blockIdx.x * blockDim.x + threadIdx.x;
    if (e >= E) return;

    const int d = __ldg(dst_idx + e);
    const int pos = atomicAdd(&g_count[d], 1);
    if (pos < MAXDEG) {
        int2 se;
        se.x = __ldg(src_idx + e);
        se.y = __float_as_int(__ldg(e_feat + e));
        g_slots[(size_t)d * MAXDEG + pos] = se;
    } else {
        int oi = atomicAdd(&g_ovf_count, 1);
        if (oi < OVF_CAP) g_ovf_edges[oi] = e;
    }
}

// ---------------------------------------------------------------------------
// Kernel 2: accumulate. 16 lanes per node; lane l owns float4 chunk l.
// Unrolled by 4 for gather MLP. Writes the FULL output row (no pre-zeroing).
// Resets g_count[node] for the next graph replay.
// ---------------------------------------------------------------------------
__global__ void accum_kernel(const float* __restrict__ emb,
                             float* __restrict__ out) {
    const int t    = blockIdx.x * blockDim.x + threadIdx.x;
    const int node = t >> 4;
    const int lane = t & 15;
    if (node >= N_NODES) return;

    int deg = g_count[node];
    if (lane == 0) g_count[node] = 0;       // self-clean for next call
    if (deg > MAXDEG) deg = MAXDEG;

    const int2* slots = g_slots + (size_t)node * MAXDEG;

    float4 acc = make_float4(0.f, 0.f, 0.f, 0.f);
    float  accE = 0.f;

    int j = 0;
    for (; j + 3 < deg; j += 4) {
        const int2 se0 = slots[j];
        const int2 se1 = slots[j + 1];
        const int2 se2 = slots[j + 2];
        const int2 se3 = slots[j + 3];
        const float4 v0 = __ldg(reinterpret_cast<const float4*>(emb + (size_t)se0.x * D_FEAT) + lane);
        const float4 v1 = __ldg(reinterpret_cast<const float4*>(emb + (size_t)se1.x * D_FEAT) + lane);
        const float4 v2 = __ldg(reinterpret_cast<const float4*>(emb + (size_t)se2.x * D_FEAT) + lane);
        const float4 v3 = __ldg(reinterpret_cast<const float4*>(emb + (size_t)se3.x * D_FEAT) + lane);
        acc.x += (v0.x + v1.x) + (v2.x + v3.x);
        acc.y += (v0.y + v1.y) + (v2.y + v3.y);
        acc.z += (v0.z + v1.z) + (v2.z + v3.z);
        acc.w += (v0.w + v1.w) + (v2.w + v3.w);
        accE  += (__int_as_float(se0.y) + __int_as_float(se1.y))
               + (__int_as_float(se2.y) + __int_as_float(se3.y));
    }
    for (; j < deg; j++) {
        const int2 se = slots[j];
        const float4 v = __ldg(reinterpret_cast<const float4*>(emb + (size_t)se.x * D_FEAT) + lane);
        acc.x += v.x; acc.y += v.y; acc.z += v.z; acc.w += v.w;
        accE  += __int_as_float(se.y);
    }

    float* row = out + (size_t)node * OUT_COLS + lane * 4;
    row[0] = acc.x;
    row[1] = acc.y;
    row[2] = acc.z;
    row[3] = acc.w;
    if (lane == 0) out[(size_t)node * OUT_COLS + D_FEAT] = accE;
}

// ---------------------------------------------------------------------------
// Kernel 3: overflow fix-up. Single block; a no-op unless some node exceeded
// MAXDEG. Runs AFTER accum's full-row writes. Resets g_ovf_count at the end.
// ---------------------------------------------------------------------------
__global__ void ovf_fix_kernel(const float* __restrict__ emb,
                               const float* __restrict__ e_feat,
                               const int*   __restrict__ src_idx,
                               const int*   __restrict__ dst_idx,
                               float* __restrict__ out) {
    int n = g_ovf_count;
    if (n > OVF_CAP) n = OVF_CAP;
    const int total = n * 16;
    for (int t = threadIdx.x; t < total; t += blockDim.x) {
        const int i    = t >> 4;
        const int lane = t & 15;
        const int e = g_ovf_edges[i];
        const int s = src_idx[e];
        const int d = dst_idx[e];
        const float4 v = __ldg(reinterpret_cast<const float4*>(emb + (size_t)s * D_FEAT) + lane);
        float* row = out + (size_t)d * OUT_COLS + lane * 4;
        atomicAdd(row + 0, v.x);
        atomicAdd(row + 1, v.y);
        atomicAdd(row + 2, v.z);
        atomicAdd(row + 3, v.w);
        if (lane == 0) atomicAdd(out + (size_t)d * OUT_COLS + D_FEAT, e_feat[e]);
    }
    __syncthreads();
    if (threadIdx.x == 0) g_ovf_count = 0;  // self-clean for next call
}

// ---------------------------------------------------------------------------
// Launch: 3 kernels (no zero pass; state self-cleans between calls)
// ---------------------------------------------------------------------------
extern "C" void kernel_launch(void* const* d_in, const int* in_sizes, int n_in,
                              void* d_out, int out_size) {
    const float* emb     = (const float*)d_in[0];   // [N, 64]
    const float* e_feat  = (const float*)d_in[1];   // [E]
    const int*   src_idx = (const int*)d_in[2];     // [E]
    const int*   dst_idx = (const int*)d_in[3];     // [E]
    float*       out     = (float*)d_out;           // [N, 65]

    const int E = in_sizes[1];

    // 1) bin edges by dst
    if (E > 0) {
        int threads = 256;
        int blocks  = (E + threads - 1) / threads;
        bin_kernel<<<blocks, threads>>>(e_feat, src_idx, dst_idx, E);
    }

    // 2) accumulate per node (writes full output, resets counters)
    {
        const long long total = (long long)N_NODES * 16;
        int threads = 256;
        int blocks  = (int)((total + threads - 1) / threads);
        accum_kernel<<<blocks, threads>>>(emb, out);
    }

    // 3) overflow fix-up (normally no-op; single block)
    if (E > 0) {
        ovf_fix_kernel<<<1, 256>>>(emb, e_feat, src_idx, dst_idx, out);
    }
}

// round 5
// speedup vs baseline: 1.7744x; 1.7744x over previous
#include <cuda_runtime.h>
#include <cstdint>

// Problem constants (fixed shapes per reference)
#define N_NODES  100000
#define D_FEAT   64
#define OUT_COLS 65
#define MAXDEG   48            // Poisson(12): P(deg>48)~0 across 100K nodes; overflow path keeps correctness
#define OVF_CAP  1300000       // >= E, overflow list can never drop edges

// Static scratch (allocation-guard-safe)
__device__ int  g_count[N_NODES];                       // per-node degree counters
__device__ int  g_ovf_count;                            // overflow edge count
__device__ int  g_ovf_edges[OVF_CAP];                   // overflow edge indices
__device__ int2 g_slots[(size_t)N_NODES * MAXDEG];      // {src_idx, bitcast(e_feat)}

// ---------------------------------------------------------------------------
// Kernel 1: zero counters (explicit; no cross-replay state coupling)
// ---------------------------------------------------------------------------
__global__ void zero_counters_kernel() {
    int i = blockIdx.x * blockDim.x + threadIdx.x;
    if (i < N_NODES) g_count[i] = 0;
    if (i == 0) g_ovf_count = 0;
}

// ---------------------------------------------------------------------------
// Kernel 2: bin edges by destination. TWO edges per thread, input loads
// hoisted before both atomics -> two independent atomic latency chains.
// ---------------------------------------------------------------------------
__global__ void bin_kernel(const float* __restrict__ e_feat,
                           const int*   __restrict__ src_idx,
                           const int*   __restrict__ dst_idx,
                           int E) {
    const int t  = blockIdx.x * blockDim.x + threadIdx.x;
    const int e0 = 2 * t;
    const int e1 = e0 + 1;
    if (e0 >= E) return;
    const bool has1 = (e1 < E);

    // Hoist ALL independent input loads before the atomics
    const int   d0 = __ldg(dst_idx + e0);
    const int   s0 = __ldg(src_idx + e0);
    const float f0 = __ldg(e_feat + e0);
    int d1 = 0, s1 = 0; float f1 = 0.f;
    if (has1) {
        d1 = __ldg(dst_idx + e1);
        s1 = __ldg(src_idx + e1);
        f1 = __ldg(e_feat + e1);
    }

    // Two independent atomic chains (overlapped ~318-cycle latencies)
    const int p0 = atomicAdd(&g_count[d0], 1);
    const int p1 = has1 ? atomicAdd(&g_count[d1], 1) : 0;

    if (p0 < MAXDEG) {
        g_slots[(size_t)d0 * MAXDEG + p0] = make_int2(s0, __float_as_int(f0));
    } else {
        int oi = atomicAdd(&g_ovf_count, 1);
        if (oi < OVF_CAP) g_ovf_edges[oi] = e0;
    }
    if (has1) {
        if (p1 < MAXDEG) {
            g_slots[(size_t)d1 * MAXDEG + p1] = make_int2(s1, __float_as_int(f1));
        } else {
            int oi = atomicAdd(&g_ovf_count, 1);
            if (oi < OVF_CAP) g_ovf_edges[oi] = e1;
        }
    }
}

// ---------------------------------------------------------------------------
// Kernel 3: accumulate. 16 lanes per node; lane l owns float4 chunk l.
// PROVEN unroll-2 form (R3). Writes full output row; no atomics.
// ---------------------------------------------------------------------------
__global__ void accum_kernel(const float* __restrict__ emb,
                             float* __restrict__ out) {
    const int t    = blockIdx.x * blockDim.x + threadIdx.x;
    const int node = t >> 4;
    const int lane = t & 15;
    if (node >= N_NODES) return;

    int deg = g_count[node];
    if (deg > MAXDEG) deg = MAXDEG;

    const int2* slots = g_slots + (size_t)node * MAXDEG;

    float4 acc = make_float4(0.f, 0.f, 0.f, 0.f);
    float  accE = 0.f;

    int j = 0;
    for (; j + 1 < deg; j += 2) {
        const int2 se0 = slots[j];
        const int2 se1 = slots[j + 1];
        const float4 v0 = __ldg(reinterpret_cast<const float4*>(emb + (size_t)se0.x * D_FEAT) + lane);
        const float4 v1 = __ldg(reinterpret_cast<const float4*>(emb + (size_t)se1.x * D_FEAT) + lane);
        acc.x += v0.x + v1.x;
        acc.y += v0.y + v1.y;
        acc.z += v0.z + v1.z;
        acc.w += v0.w + v1.w;
        accE  += __int_as_float(se0.y) + __int_as_float(se1.y);
    }
    if (j < deg) {
        const int2 se = slots[j];
        const float4 v = __ldg(reinterpret_cast<const float4*>(emb + (size_t)se.x * D_FEAT) + lane);
        acc.x += v.x; acc.y += v.y; acc.z += v.z; acc.w += v.w;
        accE  += __int_as_float(se.y);
    }

    float* row = out + (size_t)node * OUT_COLS + lane * 4;
    row[0] = acc.x;
    row[1] = acc.y;
    row[2] = acc.z;
    row[3] = acc.w;
    if (lane == 0) out[(size_t)node * OUT_COLS + D_FEAT] = accE;
}

// ---------------------------------------------------------------------------
// Kernel 4: overflow fix-up (normally a no-op). Proven R3 shape.
// ---------------------------------------------------------------------------
__global__ void ovf_fix_kernel(const float* __restrict__ emb,
                               const float* __restrict__ e_feat,
                               const int*   __restrict__ src_idx,
                               const int*   __restrict__ dst_idx,
                               float* __restrict__ out) {
    int n = g_ovf_count;
    if (n > OVF_CAP) n = OVF_CAP;
    const int total = n * 16;
    for (int t = blockIdx.x * blockDim.x + threadIdx.x; t < total;
         t += gridDim.x * blockDim.x) {
        const int i    = t >> 4;
        const int lane = t & 15;
        const int e = g_ovf_edges[i];
        const int s = src_idx[e];
        const int d = dst_idx[e];
        const float4 v = __ldg(reinterpret_cast<const float4*>(emb + (size_t)s * D_FEAT) + lane);
        float* row = out + (size_t)d * OUT_COLS + lane * 4;
        atomicAdd(row + 0, v.x);
        atomicAdd(row + 1, v.y);
        atomicAdd(row + 2, v.z);
        atomicAdd(row + 3, v.w);
        if (lane == 0) atomicAdd(out + (size_t)d * OUT_COLS + D_FEAT, e_feat[e]);
    }
}

// ---------------------------------------------------------------------------
// Launch
// ---------------------------------------------------------------------------
extern "C" void kernel_launch(void* const* d_in, const int* in_sizes, int n_in,
                              void* d_out, int out_size) {
    const float* emb     = (const float*)d_in[0];   // [N, 64]
    const float* e_feat  = (const float*)d_in[1];   // [E]
    const int*   src_idx = (const int*)d_in[2];     // [E]
    const int*   dst_idx = (const int*)d_in[3];     // [E]
    float*       out     = (float*)d_out;           // [N, 65]

    const int E = in_sizes[1];

    // 1) zero counters
    {
        int threads = 256;
        int blocks  = (N_NODES + threads - 1) / threads;
        zero_counters_kernel<<<blocks, threads>>>();
    }

    // 2) bin edges by dst (2 edges/thread)
    if (E > 0) {
        int threads = 256;
        int pairs   = (E + 1) / 2;
        int blocks  = (pairs + threads - 1) / threads;
        bin_kernel<<<blocks, threads>>>(e_feat, src_idx, dst_idx, E);
    }

    // 3) accumulate per node (writes full output)
    {
        const long long total = (long long)N_NODES * 16;
        int threads = 256;
        int blocks  = (int)((total + threads - 1) / threads);
        accum_kernel<<<blocks, threads>>>(emb, out);
    }

    // 4) overflow fix-up (normally no-op)
    if (E > 0) {
        ovf_fix_kernel<<<64, 256>>>(emb, e_feat, src_idx, dst_idx, out);
    }
}